// round 8
// baseline (speedup 1.0000x reference)
#include <cuda_runtime.h>
#include <cstddef>
#include <cstdint>

// ---------------------------------------------------------------------------
// DA-RNN: B=512, T=64, I=128, H=128, E=127
// Encoder: 64 steps of (input attention -> LSTM0 -> LSTM1)
// Decoder: 64 steps of (temporal attention -> LSTM0 -> LSTM1)
// out[b] = [h1_final, partial_final] @ proj_W.T + proj_b   (512 floats)
// ---------------------------------------------------------------------------

#define B_  512
#define T_  64
#define I_  128
#define H_  128
#define E_  127
#define SN  (B_*H_)   // 65536

// ------------------------- device scratch (static) -------------------------
__device__ float g_state[8 * SN];              // [h0p0,h0p1,c0p0,c0p1,h1p0,h1p1,c1p0,c1p1]
__device__ float g_P[(size_t)B_ * E_ * T_];    // enc attention pre-projection (B,E,64)
__device__ float g_hexp[(size_t)B_ * T_ * H_]; // encoder top hidden states (B,T,H)
__device__ float g_Hproj[(size_t)B_ * T_ * H_];// dec attention pre-projection (B,T,128)
__device__ float g_W1Te[320 * 64];             // attn_W1 transposed (320,64)
__device__ float g_W1Td[384 * 128];            // attnd_W1 transposed (384,128)
__device__ float g_xs[B_ * E_];                // scaled encoder input x_t * a
__device__ float g_din[B_];                    // decoder cell input scalar
__device__ float g_partial[B_ * H_];           // decoder context vector

// ------------------------------ math helpers -------------------------------
__device__ __forceinline__ float sigf(float x)  { return 1.0f / (1.0f + __expf(-x)); }
__device__ __forceinline__ float tanhf_(float x){ return 2.0f / (1.0f + __expf(-2.0f * x)) - 1.0f; }

// ------------------------------- utilities ---------------------------------
__global__ void darnn_zero_states(float* h0, float* c0, float* h1, float* c1) {
    int i = blockIdx.x * blockDim.x + threadIdx.x;
    if (i < SN) { h0[i] = 0.f; c0[i] = 0.f; h1[i] = 0.f; c1[i] = 0.f; }
}

// dst[c*rows + r] = src[r*cols + c]
__global__ void darnn_transpose(const float* __restrict__ src, float* __restrict__ dst,
                                int rows, int cols) {
    int idx = blockIdx.x * blockDim.x + threadIdx.x;
    if (idx < rows * cols) {
        int r = idx / cols, c = idx % cols;
        dst[c * rows + r] = src[idx];
    }
}

// ------------------ encoder attention pre-projection (once) ----------------
// P[b,e,j] = attn_b1[j] + sum_k input[b,k,e+1] * W1[j, 256+k]
// 4 (b,e) rows per block, 256 threads (j = tx&63, r = tx>>6)
__global__ void darnn_penc(const float* __restrict__ input,
                           const float* __restrict__ W1T,   // (320,64)
                           const float* __restrict__ b1,
                           float* __restrict__ P) {
    int row0 = blockIdx.x * 4;
    int tx = threadIdx.x;
    int j = tx & 63;
    int r = tx >> 6;
    int row = row0 + r;             // b*127 + e
    int b = row / E_;
    int e = row % E_;
    __shared__ float xsm[4][65];
    xsm[r][j] = input[((size_t)b * T_ + j) * I_ + 1 + e];
    __syncthreads();
    float acc = b1[j];
#pragma unroll 8
    for (int k = 0; k < 64; k++)
        acc += xsm[r][k] * W1T[(256 + k) * 64 + j];
    P[(size_t)row * 64 + j] = acc;
}

// ------------------ decoder attention pre-projection (once) ----------------
// Hproj[b,t,j] = attnd_b1[j] + sum_h hexp[b,t,h] * W1d[j, 256+h]
// block: 16 rows of (b,t); 256 threads: j = tx&127, rs = tx>>7; 8 rows/thread
__global__ void darnn_hproj(const float* __restrict__ hexp,
                            const float* __restrict__ W1dT,  // (384,128)
                            const float* __restrict__ b1d,
                            float* __restrict__ Hproj) {
    int row0 = blockIdx.x * 16;
    int tx = threadIdx.x;
    int j = tx & 127;
    int rs = tx >> 7;   // 0..1
    __shared__ float hs[16][129];
#pragma unroll
    for (int i = 0; i < 8; i++) {
        int r = (tx >> 7) + 2 * i;
        hs[r][tx & 127] = hexp[((size_t)row0 + r) * H_ + (tx & 127)];
    }
    __syncthreads();
    float acc[8];
#pragma unroll
    for (int i = 0; i < 8; i++) acc[i] = b1d[j];
    for (int k = 0; k < 128; k++) {
        float w = W1dT[(256 + k) * 128 + j];
#pragma unroll
        for (int i = 0; i < 8; i++) acc[i] += hs[rs + 2 * i][k] * w;
    }
#pragma unroll
    for (int i = 0; i < 8; i++)
        Hproj[((size_t)row0 + rs + 2 * i) * H_ + j] = acc[i];
}

// -------------------------- encoder attention step --------------------------
// one block per batch, 128 threads
__global__ void darnn_enc_attn(const float* __restrict__ input,
                               const float* __restrict__ h1, const float* __restrict__ c1,
                               const float* __restrict__ W1T,   // (320,64)
                               const float* __restrict__ W2,    // (64)
                               const float* __restrict__ b2,    // (1)
                               const float* __restrict__ P,
                               float* __restrict__ xs, int t) {
    int b = blockIdx.x;
    int tx = threadIdx.x;
    __shared__ float h1s[128], c1s[128], hvec[64], W2s[64], red[128];
    h1s[tx] = h1[b * H_ + tx];
    c1s[tx] = c1[b * H_ + tx];
    if (tx < 64) W2s[tx] = W2[tx];
    __syncthreads();
    if (tx < 64) {
        float acc = 0.f;
#pragma unroll 8
        for (int h = 0; h < 128; h++)
            acc += h1s[h] * W1T[h * 64 + tx] + c1s[h] * W1T[(128 + h) * 64 + tx];
        hvec[tx] = acc;
    }
    __syncthreads();
    float lg = -3.0e38f;
    if (tx < E_) {
        const float* Pr = P + ((size_t)b * E_ + tx) * 64;
        float acc = b2[0];
#pragma unroll 8
        for (int j = 0; j < 64; j++)
            acc += tanhf_(Pr[j] + hvec[j]) * W2s[j];
        lg = acc;
    }
    // softmax over e (127 valid)
    red[tx] = lg;
    __syncthreads();
    for (int s = 64; s > 0; s >>= 1) { if (tx < s) red[tx] = fmaxf(red[tx], red[tx + s]); __syncthreads(); }
    float m = red[0];
    __syncthreads();
    float ex = (tx < E_) ? __expf(lg - m) : 0.f;
    red[tx] = ex;
    __syncthreads();
    for (int s = 64; s > 0; s >>= 1) { if (tx < s) red[tx] += red[tx + s]; __syncthreads(); }
    float inv = 1.0f / red[0];
    if (tx < E_)
        xs[b * E_ + tx] = input[((size_t)b * T_ + t) * I_ + 1 + tx] * ex * inv;
}

// -------------------------- decoder attention step --------------------------
// one block per batch, 128 threads
__global__ void darnn_dec_attn(const float* __restrict__ input,
                               const float* __restrict__ h1, const float* __restrict__ c1,
                               const float* __restrict__ W1dT,  // (384,128)
                               const float* __restrict__ W2d,   // (128)
                               const float* __restrict__ b2d,   // (1)
                               const float* __restrict__ Hproj,
                               const float* __restrict__ hexp,
                               const float* __restrict__ decinW, // (129)
                               const float* __restrict__ decinB, // (1)
                               float* __restrict__ din,
                               float* __restrict__ partial, int t) {
    int b = blockIdx.x;
    int tx = threadIdx.x;
    __shared__ float h1s[128], c1s[128], hvec[128], W2s[128], a_s[64], red[128];
    h1s[tx] = h1[b * H_ + tx];
    c1s[tx] = c1[b * H_ + tx];
    W2s[tx] = W2d[tx];
    __syncthreads();
    {
        float acc = 0.f;
#pragma unroll 8
        for (int h = 0; h < 128; h++)
            acc += h1s[h] * W1dT[h * 128 + tx] + c1s[h] * W1dT[(128 + h) * 128 + tx];
        hvec[tx] = acc;
    }
    __syncthreads();
    float lg = -3.0e38f;
    if (tx < T_) {
        const float* Pr = Hproj + ((size_t)b * T_ + tx) * 128;
        float acc = b2d[0];
#pragma unroll 8
        for (int j = 0; j < 128; j++)
            acc += tanhf_(Pr[j] + hvec[j]) * W2s[j];
        lg = acc;
    }
    red[tx] = lg;
    __syncthreads();
    for (int s = 64; s > 0; s >>= 1) { if (tx < s) red[tx] = fmaxf(red[tx], red[tx + s]); __syncthreads(); }
    float m = red[0];
    __syncthreads();
    float ex = (tx < T_) ? __expf(lg - m) : 0.f;
    red[tx] = ex;
    __syncthreads();
    for (int s = 64; s > 0; s >>= 1) { if (tx < s) red[tx] += red[tx + s]; __syncthreads(); }
    float inv = 1.0f / red[0];
    if (tx < T_) a_s[tx] = ex * inv;
    __syncthreads();
    // context: partial[h] = sum_t a[t] * hexp[b,t,h]  (coalesced over h)
    float p = 0.f;
#pragma unroll 8
    for (int tt = 0; tt < T_; tt++)
        p += a_s[tt] * hexp[((size_t)b * T_ + tt) * H_ + tx];
    partial[b * H_ + tx] = p;
    // din[b] = sum_h p[h]*decinW[h] + decinW[128]*x_t + decinB
    red[tx] = p * decinW[tx];
    __syncthreads();
    for (int s = 64; s > 0; s >>= 1) { if (tx < s) red[tx] += red[tx + s]; __syncthreads(); }
    if (tx == 0)
        din[b] = red[0] + decinW[128] * input[((size_t)b * T_ + t) * I_ + 0] + decinB[0];
}

// ------------------------------ fused LSTM cell -----------------------------
// gates = X @ Wih^T + Hp @ Whh^T + bih + bhh ; c' = sig(f)c + sig(i)tanh(g);
// h' = sig(o)tanh(c'). grid (32,4): 16 batches x 32 h (=128 gate rows) / block.
// 128 threads: thread = (hp = tx&15 -> h pair, bg = tx>>4 -> batch pair).
__global__ void darnn_lstm_cell(const float* __restrict__ X, int Kx,
                                const float* __restrict__ Wih,
                                const float* __restrict__ Hp,
                                const float* __restrict__ Whh,
                                const float* __restrict__ bih,
                                const float* __restrict__ bhh,
                                const float* __restrict__ Cp,
                                float* __restrict__ Hout,
                                float* __restrict__ Cout,
                                float* __restrict__ Hcopy, int hstride) {
    const int b0 = blockIdx.x * 16;
    const int h0 = blockIdx.y * 32;
    const int tx = threadIdx.x;
    const int hp = tx & 15;
    const int bg = tx >> 4;
    const int lane = tx & 31;
    const int rgrp = tx >> 5;

    __shared__ float As[16][33];
    __shared__ float Bs[32][129];

    float acc[2][2][4];
#pragma unroll
    for (int a = 0; a < 2; a++)
#pragma unroll
        for (int c = 0; c < 2; c++)
#pragma unroll
            for (int g = 0; g < 4; g++) acc[a][c][g] = 0.f;

    for (int phase = 0; phase < 2; phase++) {
        const float* Ag = phase ? Hp : X;
        const float* Bg = phase ? Whh : Wih;
        const int K = phase ? H_ : Kx;
        const int ntiles = (K + 31) >> 5;
        for (int kt = 0; kt < ntiles; kt++) {
            const int kb = kt << 5;
            // load A tile: 16 rows x 32 k (coalesced over k)
            {
                int k = lane;
                int r0 = rgrp;   // 0..3
#pragma unroll
                for (int i = 0; i < 4; i++) {
                    int r = r0 + i * 4;
                    As[r][k] = (kb + k < K) ? Ag[(size_t)(b0 + r) * K + kb + k] : 0.f;
                }
            }
            // load B tile: 128 gate rows x 32 k (coalesced over k)
            {
                bool ok = (kb + lane) < K;
#pragma unroll
                for (int i = 0; i < 32; i++) {
                    int r = i * 4 + rgrp;            // 0..127
                    int g = r >> 5, hl = r & 31;
                    int j = g * H_ + h0 + hl;
                    Bs[lane][r] = ok ? Bg[(size_t)j * K + kb + lane] : 0.f;
                }
            }
            __syncthreads();
#pragma unroll
            for (int k = 0; k < 32; k++) {
                float a0 = As[2 * bg][k];
                float a1 = As[2 * bg + 1][k];
#pragma unroll
                for (int g = 0; g < 4; g++) {
                    float w0 = Bs[k][g * 32 + 2 * hp];
                    float w1 = Bs[k][g * 32 + 2 * hp + 1];
                    acc[0][0][g] += a0 * w0;
                    acc[0][1][g] += a0 * w1;
                    acc[1][0][g] += a1 * w0;
                    acc[1][1][g] += a1 * w1;
                }
            }
            __syncthreads();
        }
    }
    // epilogue: gate nonlinearity + state update
#pragma unroll
    for (int bi = 0; bi < 2; bi++) {
        int b = b0 + 2 * bg + bi;
#pragma unroll
        for (int hi = 0; hi < 2; hi++) {
            int h = h0 + 2 * hp + hi;
            float gi = acc[bi][hi][0] + bih[h]         + bhh[h];
            float gf = acc[bi][hi][1] + bih[H_ + h]    + bhh[H_ + h];
            float gg = acc[bi][hi][2] + bih[2*H_ + h]  + bhh[2*H_ + h];
            float go = acc[bi][hi][3] + bih[3*H_ + h]  + bhh[3*H_ + h];
            float cp = Cp[b * H_ + h];
            float c2 = sigf(gf) * cp + sigf(gi) * tanhf_(gg);
            float h2 = sigf(go) * tanhf_(c2);
            Cout[b * H_ + h] = c2;
            Hout[b * H_ + h] = h2;
            if (Hcopy) Hcopy[(size_t)b * hstride + h] = h2;
        }
    }
}

// ------------------------------- final output -------------------------------
__global__ void darnn_final(const float* __restrict__ h1f,
                            const float* __restrict__ partial,
                            const float* __restrict__ projW,
                            const float* __restrict__ projB,
                            float* __restrict__ out) {
    int b = blockIdx.x * blockDim.x + threadIdx.x;
    if (b < B_) {
        float acc = projB[0];
#pragma unroll 8
        for (int h = 0; h < H_; h++)
            acc += h1f[b * H_ + h] * projW[h] + partial[b * H_ + h] * projW[H_ + h];
        out[b] = acc;
    }
}

// --------------------------------- launcher ---------------------------------
extern "C" void kernel_launch(void* const* d_in, const int* in_sizes, int n_in,
                              void* d_out, int out_size) {
    const float* input    = (const float*)d_in[0];
    const float* eWih0    = (const float*)d_in[1];
    const float* eWhh0    = (const float*)d_in[2];
    const float* ebih0    = (const float*)d_in[3];
    const float* ebhh0    = (const float*)d_in[4];
    const float* eWih1    = (const float*)d_in[5];
    const float* eWhh1    = (const float*)d_in[6];
    const float* ebih1    = (const float*)d_in[7];
    const float* ebhh1    = (const float*)d_in[8];
    const float* dWih0    = (const float*)d_in[9];
    const float* dWhh0    = (const float*)d_in[10];
    const float* dbih0    = (const float*)d_in[11];
    const float* dbhh0    = (const float*)d_in[12];
    const float* dWih1    = (const float*)d_in[13];
    const float* dWhh1    = (const float*)d_in[14];
    const float* dbih1    = (const float*)d_in[15];
    const float* dbhh1    = (const float*)d_in[16];
    const float* attnW1   = (const float*)d_in[17];
    const float* attnB1   = (const float*)d_in[18];
    const float* attnW2   = (const float*)d_in[19];
    const float* attnB2   = (const float*)d_in[20];
    const float* attndW1  = (const float*)d_in[21];
    const float* attndB1  = (const float*)d_in[22];
    const float* attndW2  = (const float*)d_in[23];
    const float* attndB2  = (const float*)d_in[24];
    const float* decinW   = (const float*)d_in[25];
    const float* decinB   = (const float*)d_in[26];
    const float* projW    = (const float*)d_in[27];
    const float* projB    = (const float*)d_in[28];
    (void)in_sizes; (void)n_in; (void)out_size;

    float *st, *P, *hexp, *Hproj, *W1Te, *W1Td, *xs, *din, *part;
    cudaGetSymbolAddress((void**)&st,    g_state);
    cudaGetSymbolAddress((void**)&P,     g_P);
    cudaGetSymbolAddress((void**)&hexp,  g_hexp);
    cudaGetSymbolAddress((void**)&Hproj, g_Hproj);
    cudaGetSymbolAddress((void**)&W1Te,  g_W1Te);
    cudaGetSymbolAddress((void**)&W1Td,  g_W1Td);
    cudaGetSymbolAddress((void**)&xs,    g_xs);
    cudaGetSymbolAddress((void**)&din,   g_din);
    cudaGetSymbolAddress((void**)&part,  g_partial);

    float* h0[2] = { st + 0 * SN, st + 1 * SN };
    float* c0[2] = { st + 2 * SN, st + 3 * SN };
    float* h1[2] = { st + 4 * SN, st + 5 * SN };
    float* c1[2] = { st + 6 * SN, st + 7 * SN };

    dim3 cellGrid(32, 4);

    // one-time precomputation
    darnn_transpose<<<80, 256>>>(attnW1, W1Te, 64, 320);
    darnn_transpose<<<192, 256>>>(attndW1, W1Td, 128, 384);
    darnn_penc<<<(B_ * E_) / 4, 256>>>(input, W1Te, attnB1, P);
    darnn_zero_states<<<256, 256>>>(h0[0], c0[0], h1[0], c1[0]);

    // -------- encoder --------
    for (int t = 0; t < T_; t++) {
        int p = t & 1, q = p ^ 1;
        darnn_enc_attn<<<B_, 128>>>(input, h1[p], c1[p], W1Te, attnW2, attnB2, P, xs, t);
        darnn_lstm_cell<<<cellGrid, 128>>>(xs, E_, eWih0, h0[p], eWhh0, ebih0, ebhh0,
                                           c0[p], h0[q], c0[q], nullptr, 0);
        darnn_lstm_cell<<<cellGrid, 128>>>(h0[q], H_, eWih1, h1[p], eWhh1, ebih1, ebhh1,
                                           c1[p], h1[q], c1[q], hexp + (size_t)t * H_, T_ * H_);
    }

    // -------- decoder precompute + reset --------
    darnn_hproj<<<(B_ * T_) / 16, 256>>>(hexp, W1Td, attndB1, Hproj);
    darnn_zero_states<<<256, 256>>>(h0[0], c0[0], h1[0], c1[0]);

    // -------- decoder --------
    for (int t = 0; t < T_; t++) {
        int p = t & 1, q = p ^ 1;
        darnn_dec_attn<<<B_, 128>>>(input, h1[p], c1[p], W1Td, attndW2, attndB2,
                                    Hproj, hexp, decinW, decinB, din, part, t);
        darnn_lstm_cell<<<cellGrid, 128>>>(din, 1, dWih0, h0[p], dWhh0, dbih0, dbhh0,
                                           c0[p], h0[q], c0[q], nullptr, 0);
        darnn_lstm_cell<<<cellGrid, 128>>>(h0[q], H_, dWih1, h1[p], dWhh1, dbih1, dbhh1,
                                           c1[p], h1[q], c1[q], nullptr, 0);
    }

    darnn_final<<<4, 128>>>(h1[0], part, projW, projB, (float*)d_out);
}